// round 2
// baseline (speedup 1.0000x reference)
#include <cuda_runtime.h>
#include <math.h>

#define FDIM 64
#define NMAX 100000
#define EMAX 1600000
#define BGR  64

// ---------------- device scratch (static, no allocs) ----------------
__device__ float g_C  [NMAX * FDIM];       // per-node constant shift (dst path)
__device__ float g_ys [NMAX * FDIM];       // per-node src-path vector
__device__ float g_zx [NMAX * FDIM];       // per-node x-path of (Wo@Wl) + biases
__device__ float g_aggs[(size_t)NMAX * 768]; // [agg, agg*amp, agg/amp]
__device__ float g_out[NMAX * FDIM];       // pre-BN output
__device__ int   g_cnt [NMAX];
__device__ int   g_offs[NMAX];
__device__ int   g_fill[NMAX];
__device__ int2  g_csr [EMAX];             // (src, edge_id)
__device__ int   g_cursor;
__device__ float g_WoWl[832 * FDIM];
__device__ float g_Md[32 * FDIM], g_Ms[32 * FDIM], g_Mx[32 * FDIM];
__device__ float g_Wec[16 * FDIM];
__device__ float g_Cc[FDIM], g_csv[FDIM], g_cxv[FDIM];
__device__ float g_bnS[FDIM], g_bnQ[FDIM], g_bnA[FDIM], g_bnB[FDIM];
__device__ float g_pool[BGR * FDIM];

// ---------------- init ----------------
__global__ void k_init(int Nn) {
    int i = blockIdx.x * blockDim.x + threadIdx.x;
    if (i < Nn) g_cnt[i] = 0;
    if (i < BGR * FDIM) g_pool[i] = 0.f;
    if (i < FDIM) { g_bnS[i] = 0.f; g_bnQ[i] = 0.f; }
    if (i == 0) g_cursor = 0;
}

// ---------------- WoWl = Wo @ Wl  (832x64) ----------------
__global__ void k_wowl(const float* __restrict__ Wo, const float* __restrict__ Wl) {
    int idx = blockIdx.x * blockDim.x + threadIdx.x;
    if (idx >= 832 * FDIM) return;
    int r = idx >> 6, c = idx & 63;
    float a = 0.f;
    #pragma unroll
    for (int k = 0; k < FDIM; k++) a += Wo[r * FDIM + k] * Wl[k * FDIM + c];
    g_WoWl[idx] = a;
}

// ---------------- small folded-weight precompute ----------------
__global__ void k_small(const float* __restrict__ W2, const float* __restrict__ b2,
                        const float* __restrict__ Wp, const float* __restrict__ bp,
                        const float* __restrict__ We, const float* __restrict__ be,
                        const float* __restrict__ bo, const float* __restrict__ Wl,
                        const float* __restrict__ bl) {
    int idx = blockIdx.x * blockDim.x + threadIdx.x;
    if (idx < 2048) {                       // Md = W2 @ Wp[0:64]
        int i = idx >> 6, c = idx & 63; float a = 0.f;
        #pragma unroll
        for (int k = 0; k < 64; k++) a += W2[i * 64 + k] * Wp[k * 64 + c];
        g_Md[idx] = a;
    } else if (idx < 4096) {                // Ms = W2 @ Wp[64:128]
        int t = idx - 2048; int i = t >> 6, c = t & 63; float a = 0.f;
        #pragma unroll
        for (int k = 0; k < 64; k++) a += W2[i * 64 + k] * Wp[(64 + k) * 64 + c];
        g_Ms[t] = a;
    } else if (idx < 6144) {                // Mx = W2 @ WoWl[0:64]
        int t = idx - 4096; int i = t >> 6, c = t & 63; float a = 0.f;
        #pragma unroll
        for (int k = 0; k < 64; k++) a += W2[i * 64 + k] * g_WoWl[k * 64 + c];
        g_Mx[t] = a;
    } else if (idx < 7168) {                // Wec = We @ Wp[128:192]
        int t = idx - 6144; int i = t >> 6, c = t & 63; float a = 0.f;
        #pragma unroll
        for (int k = 0; k < 64; k++) a += We[i * 64 + k] * Wp[(128 + k) * 64 + c];
        g_Wec[t] = a;
    } else if (idx < 7232) {                // Cc = b2@WpA + be@WpC + bp
        int c = idx - 7168; float a = bp[c];
        #pragma unroll
        for (int k = 0; k < 64; k++) a += be[k] * Wp[(128 + k) * 64 + c] + b2[k] * Wp[k * 64 + c];
        g_Cc[c] = a;
    } else if (idx < 7296) {                // cs = b2@WpB
        int c = idx - 7232; float a = 0.f;
        #pragma unroll
        for (int k = 0; k < 64; k++) a += b2[k] * Wp[(64 + k) * 64 + c];
        g_csv[c] = a;
    } else if (idx < 7360) {                // cx = b2@WoWl[0:64] + bo@Wl + bl
        int c = idx - 7296; float a = bl[c];
        #pragma unroll
        for (int k = 0; k < 64; k++) a += bo[k] * Wl[k * 64 + c] + b2[k] * g_WoWl[k * 64 + c];
        g_cxv[c] = a;
    }
}

// ---------------- node pre-pass: t = relu(x@W1+b1); C, ys, zx ----------------
__global__ __launch_bounds__(256) void k_node(const float* __restrict__ x,
                                              const float* __restrict__ W1,
                                              const float* __restrict__ b1, int Nn) {
    __shared__ float sW1[64 * 32];
    __shared__ float sM[3][32 * 64];
    __shared__ float sb1[32];
    __shared__ float sC[3][64];
    int tid = threadIdx.x;
    for (int i = tid; i < 64 * 32; i += 256) sW1[i] = W1[i];
    for (int i = tid; i < 32 * 64; i += 256) {
        sM[0][i] = g_Md[i]; sM[1][i] = g_Ms[i]; sM[2][i] = g_Mx[i];
    }
    if (tid < 32) sb1[tid] = b1[tid];
    if (tid < 64) { sC[0][tid] = g_Cc[tid]; sC[1][tid] = g_csv[tid]; sC[2][tid] = g_cxv[tid]; }
    __syncthreads();
    int n = blockIdx.x * 256 + tid;
    if (n >= Nn) return;

    float xr[64];
    const float4* xp = (const float4*)(x + (size_t)n * 64);
    #pragma unroll
    for (int i = 0; i < 16; i++) {
        float4 v = xp[i];
        xr[4*i] = v.x; xr[4*i+1] = v.y; xr[4*i+2] = v.z; xr[4*i+3] = v.w;
    }
    float t[32];
    #pragma unroll
    for (int j = 0; j < 32; j += 4) {
        float a0 = sb1[j], a1 = sb1[j+1], a2 = sb1[j+2], a3 = sb1[j+3];
        #pragma unroll
        for (int i = 0; i < 64; i++) {
            float xi = xr[i];
            const float* w = &sW1[i * 32 + j];
            a0 += xi * w[0]; a1 += xi * w[1]; a2 += xi * w[2]; a3 += xi * w[3];
        }
        t[j] = fmaxf(a0, 0.f); t[j+1] = fmaxf(a1, 0.f);
        t[j+2] = fmaxf(a2, 0.f); t[j+3] = fmaxf(a3, 0.f);
    }
    float* out0 = g_C  + (size_t)n * 64;
    float* out1 = g_ys + (size_t)n * 64;
    float* out2 = g_zx + (size_t)n * 64;
    #pragma unroll
    for (int m = 0; m < 3; m++) {
        float* op = (m == 0) ? out0 : (m == 1) ? out1 : out2;
        #pragma unroll
        for (int j = 0; j < 64; j += 4) {
            float a0 = sC[m][j], a1 = sC[m][j+1], a2 = sC[m][j+2], a3 = sC[m][j+3];
            #pragma unroll
            for (int i = 0; i < 32; i++) {
                float ti = t[i];
                const float* w = &sM[m][i * 64 + j];
                a0 += ti * w[0]; a1 += ti * w[1]; a2 += ti * w[2]; a3 += ti * w[3];
            }
            float4 v; v.x = a0; v.y = a1; v.z = a2; v.w = a3;
            *(float4*)(op + j) = v;
        }
    }
}

// ---------------- CSR build ----------------
__global__ void k_count(const int* __restrict__ ei, int En) {
    int e = blockIdx.x * blockDim.x + threadIdx.x;
    if (e >= En) return;
    atomicAdd(&g_cnt[ei[En + e]], 1);
}

__global__ void k_scan(int Nn) {
    __shared__ int s[1024];
    __shared__ int base;
    int tid = threadIdx.x;
    int n = blockIdx.x * 1024 + tid;
    int c = (n < Nn) ? g_cnt[n] : 0;
    s[tid] = c;
    __syncthreads();
    for (int d = 1; d < 1024; d <<= 1) {
        int v = (tid >= d) ? s[tid - d] : 0;
        __syncthreads();
        s[tid] += v;
        __syncthreads();
    }
    if (tid == 1023) base = atomicAdd(&g_cursor, s[1023]);
    __syncthreads();
    if (n < Nn) {
        int off = base + s[tid] - c;
        g_offs[n] = off;
        g_fill[n] = off;
    }
}

__global__ void k_fill(const int* __restrict__ ei, int En) {
    int e = blockIdx.x * blockDim.x + threadIdx.x;
    if (e >= En) return;
    int d = ei[En + e];
    int s = ei[e];
    int p = atomicAdd(&g_fill[d], 1);
    g_csr[p] = make_int2(s, e);
}

// ---------------- aggregation: warp per node ----------------
__global__ __launch_bounds__(256) void k_agg(const float* __restrict__ ea, int Nn, float avg_log) {
    int lane = threadIdx.x & 31;
    int n = (blockIdx.x * 256 + threadIdx.x) >> 5;
    if (n >= Nn) return;

    float w0[16], w1[16];
    #pragma unroll
    for (int k = 0; k < 16; k++) {
        w0[k] = g_Wec[k * 64 + lane];
        w1[k] = g_Wec[k * 64 + 32 + lane];
    }
    int off = g_offs[n];
    int d0 = g_cnt[n];
    float s0 = 0.f, s1 = 0.f, q0 = 0.f, q1 = 0.f;
    float mn0 = 3.4e38f, mn1 = 3.4e38f, mx0 = -3.4e38f, mx1 = -3.4e38f;

    for (int i = 0; i < d0; i++) {
        int2 se = g_csr[off + i];
        const float4* p = (const float4*)(ea + (size_t)se.y * 16);
        float4 a0 = p[0], a1 = p[1], a2 = p[2], a3 = p[3];
        const float* yp = g_ys + (size_t)se.x * 64;
        float m0 = yp[lane], m1 = yp[32 + lane];
        m0 += a0.x*w0[0] + a0.y*w0[1] + a0.z*w0[2] + a0.w*w0[3]
            + a1.x*w0[4] + a1.y*w0[5] + a1.z*w0[6] + a1.w*w0[7]
            + a2.x*w0[8] + a2.y*w0[9] + a2.z*w0[10] + a2.w*w0[11]
            + a3.x*w0[12] + a3.y*w0[13] + a3.z*w0[14] + a3.w*w0[15];
        m1 += a0.x*w1[0] + a0.y*w1[1] + a0.z*w1[2] + a0.w*w1[3]
            + a1.x*w1[4] + a1.y*w1[5] + a1.z*w1[6] + a1.w*w1[7]
            + a2.x*w1[8] + a2.y*w1[9] + a2.z*w1[10] + a2.w*w1[11]
            + a3.x*w1[12] + a3.y*w1[13] + a3.z*w1[14] + a3.w*w1[15];
        s0 += m0; q0 += m0 * m0; mn0 = fminf(mn0, m0); mx0 = fmaxf(mx0, m0);
        s1 += m1; q1 += m1 * m1; mn1 = fminf(mn1, m1); mx1 = fmaxf(mx1, m1);
    }
    float d = (float)((d0 > 1) ? d0 : 1);
    float inv_d = 1.f / d;
    float C0 = g_C[(size_t)n * 64 + lane], C1 = g_C[(size_t)n * 64 + 32 + lane];
    float mu0 = s0 * inv_d, mu1 = s1 * inv_d;
    float sd0 = sqrtf(fmaxf(q0 * inv_d - mu0 * mu0, 0.f) + 1e-5f);
    float sd1 = sqrtf(fmaxf(q1 * inv_d - mu1 * mu1, 0.f) + 1e-5f);
    float mean0, mean1;
    if (d0 > 0) {
        mean0 = mu0 + C0; mn0 += C0; mx0 += C0;
        mean1 = mu1 + C1; mn1 += C1; mx1 += C1;
    } else {
        mean0 = 0.f; mn0 = 0.f; mx0 = 0.f;
        mean1 = 0.f; mn1 = 0.f; mx1 = 0.f;
    }
    float amp = logf(d + 1.f) / avg_log;
    float iamp = 1.f / amp;

    float* A = g_aggs + (size_t)n * 768;
    float v[8];
    v[0] = mean0; v[1] = mean1; v[2] = mn0; v[3] = mn1;
    v[4] = mx0;   v[5] = mx1;   v[6] = sd0; v[7] = sd1;
    #pragma unroll
    for (int b = 0; b < 4; b++) {
        A[b * 64 + lane]        = v[2 * b];
        A[b * 64 + 32 + lane]   = v[2 * b + 1];
        A[256 + b * 64 + lane]      = v[2 * b] * amp;
        A[256 + b * 64 + 32 + lane] = v[2 * b + 1] * amp;
        A[512 + b * 64 + lane]      = v[2 * b] * iamp;
        A[512 + b * 64 + 32 + lane] = v[2 * b + 1] * iamp;
    }
}

// ---------------- big GEMM: out = zx + aggs @ WoWl[64:832] (+BN partials) ----------------
#define BM 128
#define BK 32
__global__ __launch_bounds__(256) void k_gemm(int Nn) {
    __shared__ float sA[BM * BK];
    __shared__ float sW[BK * 64];
    __shared__ float sS[64], sQ[64];
    int tid = threadIdx.x;
    if (tid < 64) { sS[tid] = 0.f; sQ[tid] = 0.f; }
    int bm = blockIdx.x * BM;
    int r8 = (tid >> 4) << 3;
    int c4 = (tid & 15) << 2;
    float acc[8][4];
    #pragma unroll
    for (int i = 0; i < 8; i++)
        #pragma unroll
        for (int j = 0; j < 4; j++) acc[i][j] = 0.f;

    const float* Wbase = g_WoWl + 64 * 64;  // [768,64]
    for (int k0 = 0; k0 < 768; k0 += BK) {
        #pragma unroll
        for (int l = 0; l < 4; l++) {
            int lin = tid + 256 * l;
            int r = lin >> 3, kq = (lin & 7) << 2;
            int row = bm + r;
            float4 vz = make_float4(0.f, 0.f, 0.f, 0.f);
            float4 vv = (row < Nn) ? *(const float4*)(g_aggs + (size_t)row * 768 + k0 + kq) : vz;
            *(float4*)&sA[r * BK + kq] = vv;
        }
        #pragma unroll
        for (int l = 0; l < 2; l++) {
            int lin = tid + 256 * l;
            int k = lin >> 4, cq = (lin & 15) << 2;
            *(float4*)&sW[k * 64 + cq] = *(const float4*)(Wbase + (size_t)(k0 + k) * 64 + cq);
        }
        __syncthreads();
        #pragma unroll
        for (int kk = 0; kk < BK; kk++) {
            float4 w = *(float4*)&sW[kk * 64 + c4];
            #pragma unroll
            for (int ii = 0; ii < 8; ii++) {
                float a = sA[(r8 + ii) * BK + kk];
                acc[ii][0] += a * w.x; acc[ii][1] += a * w.y;
                acc[ii][2] += a * w.z; acc[ii][3] += a * w.w;
            }
        }
        __syncthreads();
    }
    float lS[4] = {0.f, 0.f, 0.f, 0.f};
    float lQ[4] = {0.f, 0.f, 0.f, 0.f};
    #pragma unroll
    for (int ii = 0; ii < 8; ii++) {
        int row = bm + r8 + ii;
        if (row < Nn) {
            const float* zp = g_zx + (size_t)row * 64 + c4;
            float4 o;
            o.x = zp[0] + acc[ii][0];
            o.y = zp[1] + acc[ii][1];
            o.z = zp[2] + acc[ii][2];
            o.w = zp[3] + acc[ii][3];
            *(float4*)(g_out + (size_t)row * 64 + c4) = o;
            lS[0] += o.x; lQ[0] += o.x * o.x;
            lS[1] += o.y; lQ[1] += o.y * o.y;
            lS[2] += o.z; lQ[2] += o.z * o.z;
            lS[3] += o.w; lQ[3] += o.w * o.w;
        }
    }
    #pragma unroll
    for (int j = 0; j < 4; j++) {
        atomicAdd(&sS[c4 + j], lS[j]);
        atomicAdd(&sQ[c4 + j], lQ[j]);
    }
    __syncthreads();
    if (tid < 64) {
        atomicAdd(&g_bnS[tid], sS[tid]);
        atomicAdd(&g_bnQ[tid], sQ[tid]);
    }
}

// ---------------- BN finalize ----------------
__global__ void k_bn(const float* __restrict__ gamma, const float* __restrict__ beta, int Nn) {
    int f = threadIdx.x;
    if (f >= 64) return;
    float inv_n = 1.f / (float)Nn;
    float mu = g_bnS[f] * inv_n;
    float var = g_bnQ[f] * inv_n - mu * mu;
    float sc = gamma[f] * rsqrtf(var + 1e-5f);
    g_bnA[f] = sc;
    g_bnB[f] = beta[f] - mu * sc;
}

// ---------------- pooling (batch sorted -> local segment accumulation) ----------------
__global__ void k_pool(const int* __restrict__ batch, int Nn) {
    int f = threadIdx.x & 63;
    int g = threadIdx.x >> 6;
    int n0 = blockIdx.x * 1024;
    float sc = g_bnA[f], sh = g_bnB[f];
    float acc = 0.f;
    int cur = -1;
    for (int i = g; i < 1024; i += 4) {
        int n = n0 + i;
        if (n >= Nn) break;
        int b = batch[n];
        float v = fmaxf(g_out[(size_t)n * 64 + f] * sc + sh, 0.f);
        if (b != cur) {
            if (cur >= 0) atomicAdd(&g_pool[cur * 64 + f], acc);
            cur = b; acc = v;
        } else {
            acc += v;
        }
    }
    if (cur >= 0) atomicAdd(&g_pool[cur * 64 + f], acc);
}

// ---------------- head MLP ----------------
__global__ void k_head(const float* __restrict__ Wm1, const float* __restrict__ bm1,
                       const float* __restrict__ Wm2, const float* __restrict__ bm2,
                       float* __restrict__ outp) {
    __shared__ float sp[64];
    __shared__ float red[128];
    int b = blockIdx.x, j = threadIdx.x;
    if (j < 64) sp[j] = g_pool[b * 64 + j];
    __syncthreads();
    float v = 0.f;
    if (j < 100) {
        float a = bm1[j];
        #pragma unroll
        for (int k = 0; k < 64; k++) a += sp[k] * Wm1[k * 100 + j];
        v = fmaxf(a, 0.f) * Wm2[j];
    }
    red[j] = v;
    __syncthreads();
    for (int st = 64; st > 0; st >>= 1) {
        if (j < st) red[j] += red[j + st];
        __syncthreads();
    }
    if (j == 0) outp[b] = red[0] + bm2[0];
}

// ---------------- launch ----------------
extern "C" void kernel_launch(void* const* d_in, const int* in_sizes, int n_in,
                              void* d_out, int out_size) {
    const float* x    = (const float*)d_in[0];
    const float* ea   = (const float*)d_in[1];
    const int*   ei   = (const int*)  d_in[2];
    const int*   batch= (const int*)  d_in[3];
    const float* W1   = (const float*)d_in[4];
    const float* b1   = (const float*)d_in[5];
    const float* W2   = (const float*)d_in[6];
    const float* b2   = (const float*)d_in[7];
    const float* We   = (const float*)d_in[8];
    const float* be   = (const float*)d_in[9];
    const float* Wp   = (const float*)d_in[10];
    const float* bp   = (const float*)d_in[11];
    const float* Wo   = (const float*)d_in[12];
    const float* bo   = (const float*)d_in[13];
    const float* Wl   = (const float*)d_in[14];
    const float* bl   = (const float*)d_in[15];
    const float* gamma= (const float*)d_in[16];
    const float* beta = (const float*)d_in[17];
    const float* Wm1  = (const float*)d_in[18];
    const float* bm1  = (const float*)d_in[19];
    const float* Wm2  = (const float*)d_in[20];
    const float* bm2  = (const float*)d_in[21];

    int N = in_sizes[0] / FDIM;
    int E = in_sizes[1] / 16;

    // AVG_LOG (matches reference float64 computation)
    static const double DEG[17] = {0,1000,2000,4000,8000,16000,24000,20000,12000,
                                   6000,3000,2000,1000,500,300,200,100};
    double snum = 0.0, sden = 0.0;
    for (int i = 0; i < 17; i++) { snum += log((double)i + 1.0) * DEG[i]; sden += DEG[i]; }
    float avg_log = (float)(snum / sden);

    int nb256  = (N + 255) / 256;
    int eb256  = (E + 255) / 256;

    k_init <<<nb256, 256>>>(N);
    k_wowl <<<(832 * FDIM + 255) / 256, 256>>>(Wo, Wl);
    k_small<<<(7360 + 255) / 256, 256>>>(W2, b2, Wp, bp, We, be, bo, Wl, bl);
    k_node <<<nb256, 256>>>(x, W1, b1, N);
    k_count<<<eb256, 256>>>(ei, E);
    k_scan <<<(N + 1023) / 1024, 1024>>>(N);
    k_fill <<<eb256, 256>>>(ei, E);
    k_agg  <<<(N + 7) / 8, 256>>>(ea, N, avg_log);
    k_gemm <<<(N + BM - 1) / BM, 256>>>(N);
    k_bn   <<<1, 64>>>(gamma, beta, N);
    k_pool <<<(N + 1023) / 1024, 256>>>(batch, N);
    k_head <<<BGR, 128>>>(Wm1, bm1, Wm2, bm2, (float*)d_out);
}

// round 3
// speedup vs baseline: 1.0170x; 1.0170x over previous
#include <cuda_runtime.h>
#include <math.h>

#define FDIM 64
#define NMAX 100000
#define EMAX 1600000
#define BGR  64

typedef unsigned long long ull;

// ---------------- f32x2 helpers ----------------
__device__ __forceinline__ void fma2(ull& acc, ull a, ull b) {
    asm("fma.rn.f32x2 %0, %1, %2, %0;" : "+l"(acc) : "l"(a), "l"(b));
}
__device__ __forceinline__ ull bpack(float f) {            // (f, f)
    ull o; unsigned u = __float_as_uint(f);
    asm("mov.b64 %0, {%1, %1};" : "=l"(o) : "r"(u));
    return o;
}
__device__ __forceinline__ ull pack2(float lo, float hi) {
    ull o;
    asm("mov.b64 %0, {%1, %2};" : "=l"(o) : "r"(__float_as_uint(lo)), "r"(__float_as_uint(hi)));
    return o;
}
__device__ __forceinline__ void unpack2(ull v, float& lo, float& hi) {
    unsigned a, b;
    asm("mov.b64 {%0, %1}, %2;" : "=r"(a), "=r"(b) : "l"(v));
    lo = __uint_as_float(a); hi = __uint_as_float(b);
}

// ---------------- device scratch (static, no allocs) ----------------
__device__ __align__(16) float g_C  [NMAX * FDIM];
__device__ __align__(16) float g_ys [NMAX * FDIM];
__device__ __align__(16) float g_zx [NMAX * FDIM];
__device__ __align__(16) float g_agg[(size_t)NMAX * 256];   // [mean|mn|mx|std]
__device__ float g_amp [NMAX];
__device__ float g_iamp[NMAX];
__device__ __align__(16) float g_out[NMAX * FDIM];
__device__ int   g_cnt [NMAX];
__device__ int   g_offs[NMAX];
__device__ int   g_fill[NMAX];
__device__ int2  g_csr [EMAX];
__device__ int   g_cursor;
__device__ __align__(16) float g_WoWl[832 * FDIM];
__device__ __align__(16) float g_Md[32 * FDIM], g_Ms[32 * FDIM], g_Mx[32 * FDIM];
__device__ __align__(16) float g_Wec[16 * FDIM];
__device__ float g_Cc[FDIM], g_csv[FDIM], g_cxv[FDIM];
__device__ float g_bnS[FDIM], g_bnQ[FDIM], g_bnA[FDIM], g_bnB[FDIM];
__device__ float g_pool[BGR * FDIM];

// ---------------- init ----------------
__global__ void k_init(int Nn) {
    int i = blockIdx.x * blockDim.x + threadIdx.x;
    if (i < Nn) g_cnt[i] = 0;
    if (i < BGR * FDIM) g_pool[i] = 0.f;
    if (i < FDIM) { g_bnS[i] = 0.f; g_bnQ[i] = 0.f; }
    if (i == 0) g_cursor = 0;
}

// ---------------- WoWl = Wo @ Wl  (832x64) ----------------
__global__ void k_wowl(const float* __restrict__ Wo, const float* __restrict__ Wl) {
    int idx = blockIdx.x * blockDim.x + threadIdx.x;
    if (idx >= 832 * FDIM) return;
    int r = idx >> 6, c = idx & 63;
    float a = 0.f;
    #pragma unroll
    for (int k = 0; k < FDIM; k++) a += Wo[r * FDIM + k] * Wl[k * FDIM + c];
    g_WoWl[idx] = a;
}

// ---------------- small folded-weight precompute ----------------
__global__ void k_small(const float* __restrict__ W2, const float* __restrict__ b2,
                        const float* __restrict__ Wp, const float* __restrict__ bp,
                        const float* __restrict__ We, const float* __restrict__ be,
                        const float* __restrict__ bo, const float* __restrict__ Wl,
                        const float* __restrict__ bl) {
    int idx = blockIdx.x * blockDim.x + threadIdx.x;
    if (idx < 2048) {                       // Md = W2 @ Wp[0:64]
        int i = idx >> 6, c = idx & 63; float a = 0.f;
        #pragma unroll
        for (int k = 0; k < 64; k++) a += W2[i * 64 + k] * Wp[k * 64 + c];
        g_Md[idx] = a;
    } else if (idx < 4096) {                // Ms = W2 @ Wp[64:128]
        int t = idx - 2048; int i = t >> 6, c = t & 63; float a = 0.f;
        #pragma unroll
        for (int k = 0; k < 64; k++) a += W2[i * 64 + k] * Wp[(64 + k) * 64 + c];
        g_Ms[t] = a;
    } else if (idx < 6144) {                // Mx = W2 @ WoWl[0:64]
        int t = idx - 4096; int i = t >> 6, c = t & 63; float a = 0.f;
        #pragma unroll
        for (int k = 0; k < 64; k++) a += W2[i * 64 + k] * g_WoWl[k * 64 + c];
        g_Mx[t] = a;
    } else if (idx < 7168) {                // Wec = We @ Wp[128:192]
        int t = idx - 6144; int i = t >> 6, c = t & 63; float a = 0.f;
        #pragma unroll
        for (int k = 0; k < 64; k++) a += We[i * 64 + k] * Wp[(128 + k) * 64 + c];
        g_Wec[t] = a;
    } else if (idx < 7232) {                // Cc = b2@WpA + be@WpC + bp
        int c = idx - 7168; float a = bp[c];
        #pragma unroll
        for (int k = 0; k < 64; k++) a += be[k] * Wp[(128 + k) * 64 + c] + b2[k] * Wp[k * 64 + c];
        g_Cc[c] = a;
    } else if (idx < 7296) {                // cs = b2@WpB
        int c = idx - 7232; float a = 0.f;
        #pragma unroll
        for (int k = 0; k < 64; k++) a += b2[k] * Wp[(64 + k) * 64 + c];
        g_csv[c] = a;
    } else if (idx < 7360) {                // cx = b2@WoWl[0:64] + bo@Wl + bl
        int c = idx - 7296; float a = bl[c];
        #pragma unroll
        for (int k = 0; k < 64; k++) a += bo[k] * Wl[k * 64 + c] + b2[k] * g_WoWl[k * 64 + c];
        g_cxv[c] = a;
    }
}

// ---------------- node pre-pass (f32x2): t = relu(x@W1+b1); C, ys, zx ----------------
__global__ __launch_bounds__(256) void k_node(const float* __restrict__ x,
                                              const float* __restrict__ W1,
                                              const float* __restrict__ b1, int Nn) {
    __shared__ __align__(16) float sW1[64 * 32];
    __shared__ __align__(16) float sM[3][32 * 64];
    __shared__ float sb1[32];
    __shared__ float sC[3][64];
    int tid = threadIdx.x;
    for (int i = tid; i < 64 * 32; i += 256) sW1[i] = W1[i];
    for (int i = tid; i < 32 * 64; i += 256) {
        sM[0][i] = g_Md[i]; sM[1][i] = g_Ms[i]; sM[2][i] = g_Mx[i];
    }
    if (tid < 32) sb1[tid] = b1[tid];
    if (tid < 64) { sC[0][tid] = g_Cc[tid]; sC[1][tid] = g_csv[tid]; sC[2][tid] = g_cxv[tid]; }
    __syncthreads();
    int n = blockIdx.x * 256 + tid;
    if (n >= Nn) return;

    // phase 1: t = relu(x @ W1 + b1), accumulated as 16 f32x2 pairs
    ull tacc[16];
    #pragma unroll
    for (int j = 0; j < 16; j++) tacc[j] = pack2(sb1[2 * j], sb1[2 * j + 1]);
    const float4* xp = (const float4*)(x + (size_t)n * 64);
    #pragma unroll
    for (int i = 0; i < 16; i++) {
        float4 xv = xp[i];
        float xs[4] = {xv.x, xv.y, xv.z, xv.w};
        #pragma unroll
        for (int c = 0; c < 4; c++) {
            ull xb = bpack(xs[c]);
            const ulonglong2* wr = (const ulonglong2*)&sW1[(4 * i + c) * 32];
            #pragma unroll
            for (int q = 0; q < 8; q++) {
                ulonglong2 w = wr[q];
                fma2(tacc[2 * q], xb, w.x);
                fma2(tacc[2 * q + 1], xb, w.y);
            }
        }
    }
    float t[32];
    #pragma unroll
    for (int j = 0; j < 16; j++) {
        float lo, hi; unpack2(tacc[j], lo, hi);
        t[2 * j]     = fmaxf(lo, 0.f);
        t[2 * j + 1] = fmaxf(hi, 0.f);
    }

    // phase 2: three 32x64 mats
    float* outs0 = g_C  + (size_t)n * 64;
    float* outs1 = g_ys + (size_t)n * 64;
    float* outs2 = g_zx + (size_t)n * 64;
    #pragma unroll
    for (int m = 0; m < 3; m++) {
        ull acc[32];
        #pragma unroll
        for (int j = 0; j < 32; j++) acc[j] = pack2(sC[m][2 * j], sC[m][2 * j + 1]);
        #pragma unroll
        for (int k = 0; k < 32; k++) {
            ull tb = bpack(t[k]);
            const ulonglong2* wr = (const ulonglong2*)&sM[m][k * 64];
            #pragma unroll
            for (int q = 0; q < 16; q++) {
                ulonglong2 w = wr[q];
                fma2(acc[2 * q], tb, w.x);
                fma2(acc[2 * q + 1], tb, w.y);
            }
        }
        float* op = (m == 0) ? outs0 : (m == 1) ? outs1 : outs2;
        #pragma unroll
        for (int q = 0; q < 16; q++) {
            ulonglong2 v; v.x = acc[2 * q]; v.y = acc[2 * q + 1];
            *(ulonglong2*)(op + 4 * q) = v;
        }
    }
}

// ---------------- CSR build ----------------
__global__ void k_count(const int* __restrict__ ei, int En) {
    int e = blockIdx.x * blockDim.x + threadIdx.x;
    if (e >= En) return;
    atomicAdd(&g_cnt[ei[En + e]], 1);
}

__global__ void k_scan(int Nn) {
    __shared__ int s[1024];
    __shared__ int base;
    int tid = threadIdx.x;
    int n = blockIdx.x * 1024 + tid;
    int c = (n < Nn) ? g_cnt[n] : 0;
    s[tid] = c;
    __syncthreads();
    for (int d = 1; d < 1024; d <<= 1) {
        int v = (tid >= d) ? s[tid - d] : 0;
        __syncthreads();
        s[tid] += v;
        __syncthreads();
    }
    if (tid == 1023) base = atomicAdd(&g_cursor, s[1023]);
    __syncthreads();
    if (n < Nn) {
        int off = base + s[tid] - c;
        g_offs[n] = off;
        g_fill[n] = off;
    }
}

__global__ void k_fill(const int* __restrict__ ei, int En) {
    int e = blockIdx.x * blockDim.x + threadIdx.x;
    if (e >= En) return;
    int d = ei[En + e];
    int s = ei[e];
    int p = atomicAdd(&g_fill[d], 1);
    g_csr[p] = make_int2(s, e);
}

// ---------------- aggregation: warp per node ----------------
__global__ __launch_bounds__(256) void k_agg(const float* __restrict__ ea, int Nn, float avg_log) {
    int lane = threadIdx.x & 31;
    int n = (blockIdx.x * 256 + threadIdx.x) >> 5;
    if (n >= Nn) return;

    float w0[16], w1[16];
    #pragma unroll
    for (int k = 0; k < 16; k++) {
        w0[k] = g_Wec[k * 64 + lane];
        w1[k] = g_Wec[k * 64 + 32 + lane];
    }
    int off = g_offs[n];
    int d0 = g_cnt[n];
    float s0 = 0.f, s1 = 0.f, q0 = 0.f, q1 = 0.f;
    float mn0 = 3.4e38f, mn1 = 3.4e38f, mx0 = -3.4e38f, mx1 = -3.4e38f;

    for (int i = 0; i < d0; i++) {
        int2 se = g_csr[off + i];
        const float4* p = (const float4*)(ea + (size_t)se.y * 16);
        float4 a0 = p[0], a1 = p[1], a2 = p[2], a3 = p[3];
        const float* yp = g_ys + (size_t)se.x * 64;
        float m0 = yp[lane], m1 = yp[32 + lane];
        m0 += a0.x*w0[0] + a0.y*w0[1] + a0.z*w0[2] + a0.w*w0[3]
            + a1.x*w0[4] + a1.y*w0[5] + a1.z*w0[6] + a1.w*w0[7]
            + a2.x*w0[8] + a2.y*w0[9] + a2.z*w0[10] + a2.w*w0[11]
            + a3.x*w0[12] + a3.y*w0[13] + a3.z*w0[14] + a3.w*w0[15];
        m1 += a0.x*w1[0] + a0.y*w1[1] + a0.z*w1[2] + a0.w*w1[3]
            + a1.x*w1[4] + a1.y*w1[5] + a1.z*w1[6] + a1.w*w1[7]
            + a2.x*w1[8] + a2.y*w1[9] + a2.z*w1[10] + a2.w*w1[11]
            + a3.x*w1[12] + a3.y*w1[13] + a3.z*w1[14] + a3.w*w1[15];
        s0 += m0; q0 += m0 * m0; mn0 = fminf(mn0, m0); mx0 = fmaxf(mx0, m0);
        s1 += m1; q1 += m1 * m1; mn1 = fminf(mn1, m1); mx1 = fmaxf(mx1, m1);
    }
    float d = (float)((d0 > 1) ? d0 : 1);
    float inv_d = 1.f / d;
    float C0 = g_C[(size_t)n * 64 + lane], C1 = g_C[(size_t)n * 64 + 32 + lane];
    float mu0 = s0 * inv_d, mu1 = s1 * inv_d;
    float sd0 = sqrtf(fmaxf(q0 * inv_d - mu0 * mu0, 0.f) + 1e-5f);
    float sd1 = sqrtf(fmaxf(q1 * inv_d - mu1 * mu1, 0.f) + 1e-5f);
    float mean0, mean1;
    if (d0 > 0) {
        mean0 = mu0 + C0; mn0 += C0; mx0 += C0;
        mean1 = mu1 + C1; mn1 += C1; mx1 += C1;
    } else {
        mean0 = 0.f; mn0 = 0.f; mx0 = 0.f;
        mean1 = 0.f; mn1 = 0.f; mx1 = 0.f;
    }
    float amp = logf(d + 1.f) / avg_log;
    float iamp = 1.f / amp;

    float* A = g_agg + (size_t)n * 256;
    A[lane]       = mean0; A[32 + lane]  = mean1;
    A[64 + lane]  = mn0;   A[96 + lane]  = mn1;
    A[128 + lane] = mx0;   A[160 + lane] = mx1;
    A[192 + lane] = sd0;   A[224 + lane] = sd1;
    if (lane == 0) { g_amp[n] = amp; g_iamp[n] = iamp; }
}

// ---------------- big GEMM: out = zx + agg@(Wa + amp*Wb + iamp*Wc) ----------------
#define BM 128
#define BK 32
__global__ __launch_bounds__(512) void k_gemm(int Nn) {
    __shared__ __align__(16) float sA[BM * BK];
    __shared__ __align__(16) float sW[3][BK * 64];
    __shared__ float sS[64], sQ[64];
    int tid = threadIdx.x;
    if (tid < 64) { sS[tid] = 0.f; sQ[tid] = 0.f; }
    int bm = blockIdx.x * BM;
    int rg = tid >> 4;          // 0..31 row groups of 4
    int c4 = (tid & 15) << 2;   // col group of 4

    ull acc[3][4][2];
    #pragma unroll
    for (int m = 0; m < 3; m++)
        #pragma unroll
        for (int i = 0; i < 4; i++) { acc[m][i][0] = 0ull; acc[m][i][1] = 0ull; }

    for (int k0 = 0; k0 < 256; k0 += BK) {
        #pragma unroll
        for (int l = 0; l < 2; l++) {
            int lin = tid + 512 * l;                 // 0..1023
            int r = lin >> 3, kq = (lin & 7) << 2;
            int row = bm + r;
            float4 vz = make_float4(0.f, 0.f, 0.f, 0.f);
            float4 vv = (row < Nn) ? *(const float4*)(g_agg + (size_t)row * 256 + k0 + kq) : vz;
            *(float4*)&sA[r * BK + kq] = vv;
        }
        #pragma unroll
        for (int l = 0; l < 3; l++) {
            int lin = tid + 512 * l;                 // 0..1535
            int m = lin >> 9, t2 = lin & 511;
            int k = t2 >> 4, cq = (t2 & 15) << 2;
            *(float4*)&sW[m][k * 64 + cq] =
                *(const float4*)(g_WoWl + (size_t)(64 + m * 256 + k0 + k) * 64 + cq);
        }
        __syncthreads();
        #pragma unroll
        for (int kk = 0; kk < BK; kk++) {
            ulonglong2 wa = *(const ulonglong2*)&sW[0][kk * 64 + c4];
            ulonglong2 wb = *(const ulonglong2*)&sW[1][kk * 64 + c4];
            ulonglong2 wc = *(const ulonglong2*)&sW[2][kk * 64 + c4];
            #pragma unroll
            for (int ii = 0; ii < 4; ii++) {
                ull a2 = bpack(sA[(rg * 4 + ii) * BK + kk]);
                fma2(acc[0][ii][0], a2, wa.x); fma2(acc[0][ii][1], a2, wa.y);
                fma2(acc[1][ii][0], a2, wb.x); fma2(acc[1][ii][1], a2, wb.y);
                fma2(acc[2][ii][0], a2, wc.x); fma2(acc[2][ii][1], a2, wc.y);
            }
        }
        __syncthreads();
    }

    float lS[4] = {0.f, 0.f, 0.f, 0.f};
    float lQ[4] = {0.f, 0.f, 0.f, 0.f};
    #pragma unroll
    for (int ii = 0; ii < 4; ii++) {
        int row = bm + rg * 4 + ii;
        if (row < Nn) {
            float amp = g_amp[row], ia = g_iamp[row];
            float4 z = *(const float4*)(g_zx + (size_t)row * 64 + c4);
            float o[4];
            #pragma unroll
            for (int j = 0; j < 2; j++) {
                float A0, A1, B0, B1, Cv0, Cv1;
                unpack2(acc[0][ii][j], A0, A1);
                unpack2(acc[1][ii][j], B0, B1);
                unpack2(acc[2][ii][j], Cv0, Cv1);
                o[2 * j]     = A0 + amp * B0 + ia * Cv0;
                o[2 * j + 1] = A1 + amp * B1 + ia * Cv1;
            }
            o[0] += z.x; o[1] += z.y; o[2] += z.z; o[3] += z.w;
            float4 ov; ov.x = o[0]; ov.y = o[1]; ov.z = o[2]; ov.w = o[3];
            *(float4*)(g_out + (size_t)row * 64 + c4) = ov;
            #pragma unroll
            for (int j = 0; j < 4; j++) { lS[j] += o[j]; lQ[j] += o[j] * o[j]; }
        }
    }
    #pragma unroll
    for (int j = 0; j < 4; j++) {
        atomicAdd(&sS[c4 + j], lS[j]);
        atomicAdd(&sQ[c4 + j], lQ[j]);
    }
    __syncthreads();
    if (tid < 64) {
        atomicAdd(&g_bnS[tid], sS[tid]);
        atomicAdd(&g_bnQ[tid], sQ[tid]);
    }
}

// ---------------- BN finalize ----------------
__global__ void k_bn(const float* __restrict__ gamma, const float* __restrict__ beta, int Nn) {
    int f = threadIdx.x;
    if (f >= 64) return;
    float inv_n = 1.f / (float)Nn;
    float mu = g_bnS[f] * inv_n;
    float var = g_bnQ[f] * inv_n - mu * mu;
    float sc = gamma[f] * rsqrtf(var + 1e-5f);
    g_bnA[f] = sc;
    g_bnB[f] = beta[f] - mu * sc;
}

// ---------------- pooling ----------------
__global__ void k_pool(const int* __restrict__ batch, int Nn) {
    int f = threadIdx.x & 63;
    int g = threadIdx.x >> 6;
    int n0 = blockIdx.x * 1024;
    float sc = g_bnA[f], sh = g_bnB[f];
    float acc = 0.f;
    int cur = -1;
    for (int i = g; i < 1024; i += 4) {
        int n = n0 + i;
        if (n >= Nn) break;
        int b = batch[n];
        float v = fmaxf(g_out[(size_t)n * 64 + f] * sc + sh, 0.f);
        if (b != cur) {
            if (cur >= 0) atomicAdd(&g_pool[cur * 64 + f], acc);
            cur = b; acc = v;
        } else {
            acc += v;
        }
    }
    if (cur >= 0) atomicAdd(&g_pool[cur * 64 + f], acc);
}

// ---------------- head MLP ----------------
__global__ void k_head(const float* __restrict__ Wm1, const float* __restrict__ bm1,
                       const float* __restrict__ Wm2, const float* __restrict__ bm2,
                       float* __restrict__ outp) {
    __shared__ float sp[64];
    __shared__ float red[128];
    int b = blockIdx.x, j = threadIdx.x;
    if (j < 64) sp[j] = g_pool[b * 64 + j];
    __syncthreads();
    float v = 0.f;
    if (j < 100) {
        float a = bm1[j];
        #pragma unroll
        for (int k = 0; k < 64; k++) a += sp[k] * Wm1[k * 100 + j];
        v = fmaxf(a, 0.f) * Wm2[j];
    }
    red[j] = v;
    __syncthreads();
    for (int st = 64; st > 0; st >>= 1) {
        if (j < st) red[j] += red[j + st];
        __syncthreads();
    }
    if (j == 0) outp[b] = red[0] + bm2[0];
}

// ---------------- launch ----------------
extern "C" void kernel_launch(void* const* d_in, const int* in_sizes, int n_in,
                              void* d_out, int out_size) {
    const float* x    = (const float*)d_in[0];
    const float* ea   = (const float*)d_in[1];
    const int*   ei   = (const int*)  d_in[2];
    const int*   batch= (const int*)  d_in[3];
    const float* W1   = (const float*)d_in[4];
    const float* b1   = (const float*)d_in[5];
    const float* W2   = (const float*)d_in[6];
    const float* b2   = (const float*)d_in[7];
    const float* We   = (const float*)d_in[8];
    const float* be   = (const float*)d_in[9];
    const float* Wp   = (const float*)d_in[10];
    const float* bp   = (const float*)d_in[11];
    const float* Wo   = (const float*)d_in[12];
    const float* bo   = (const float*)d_in[13];
    const float* Wl   = (const float*)d_in[14];
    const float* bl   = (const float*)d_in[15];
    const float* gamma= (const float*)d_in[16];
    const float* beta = (const float*)d_in[17];
    const float* Wm1  = (const float*)d_in[18];
    const float* bm1  = (const float*)d_in[19];
    const float* Wm2  = (const float*)d_in[20];
    const float* bm2  = (const float*)d_in[21];

    int N = in_sizes[0] / FDIM;
    int E = in_sizes[1] / 16;

    static const double DEG[17] = {0,1000,2000,4000,8000,16000,24000,20000,12000,
                                   6000,3000,2000,1000,500,300,200,100};
    double snum = 0.0, sden = 0.0;
    for (int i = 0; i < 17; i++) { snum += log((double)i + 1.0) * DEG[i]; sden += DEG[i]; }
    float avg_log = (float)(snum / sden);

    int nb256 = (N + 255) / 256;
    int eb256 = (E + 255) / 256;

    k_init <<<nb256, 256>>>(N);
    k_wowl <<<(832 * FDIM + 255) / 256, 256>>>(Wo, Wl);
    k_small<<<(7360 + 255) / 256, 256>>>(W2, b2, Wp, bp, We, be, bo, Wl, bl);
    k_node <<<nb256, 256>>>(x, W1, b1, N);
    k_count<<<eb256, 256>>>(ei, E);
    k_scan <<<(N + 1023) / 1024, 1024>>>(N);
    k_fill <<<eb256, 256>>>(ei, E);
    k_agg  <<<(N + 7) / 8, 256>>>(ea, N, avg_log);
    k_gemm <<<(N + BM - 1) / BM, 512>>>(N);
    k_bn   <<<1, 64>>>(gamma, beta, N);
    k_pool <<<(N + 1023) / 1024, 256>>>(batch, N);
    k_head <<<BGR, 128>>>(Wm1, bm1, Wm2, bm2, (float*)d_out);
}